// round 16
// baseline (speedup 1.0000x reference)
#include <cuda_runtime.h>
#include <cuda_bf16.h>

#define MARGIN 0.5f
#define EPS 1e-6f
#define WARPS_PER_BLOCK 8
#define THREADS (WARPS_PER_BLOCK * 32)
#define NSM 148
#define BLOCKS_PER_SM 4

// Allocation-free scratch; last finishing block resets for graph replays.
__device__ double g_sum = 0.0;
__device__ unsigned int g_count = 0u;

__device__ __forceinline__ float dsq(const float4 a, const float4 b)
{
    float d0 = a.x - b.x + EPS;
    float d1 = a.y - b.y + EPS;
    float d2 = a.z - b.z + EPS;
    float d3 = a.w - b.w + EPS;
    return fmaf(d0, d0, fmaf(d1, d1, fmaf(d2, d2, d3 * d3)));
}

// Paired reduction over a 16-lane half (5 shuffles for both sums + both sqrts).
// Returns relu(d_pos - d_neg + MARGIN) valid on lanes with (lane&15)==0.
__device__ __forceinline__ float reduce_pair(float sp, float sn, int lane)
{
    const unsigned full = 0xFFFFFFFFu;
    const bool hi = (lane & 8) != 0;
    float send = hi ? sp : sn;
    float recv = __shfl_xor_sync(full, send, 8, 16);
    float v = (hi ? sn : sp) + recv;      // lo lanes: sp pair-sum, hi lanes: sn
    v += __shfl_xor_sync(full, v, 4, 16);
    v += __shfl_xor_sync(full, v, 2, 16);
    v += __shfl_xor_sync(full, v, 1, 16);
    float d = sqrtf(v);                   // lo: d_pos, hi: d_neg
    float o = __shfl_xor_sync(full, d, 8, 16);
    return fmaxf(d - o + MARGIN, 0.0f);   // valid where !hi; read at sl==0
}

// The proven group-of-4 body (half-warp per triplet, dense 256B addressing,
// 12 gathers in flight). Negatives use __ldcs: zero-reuse streaming data,
// evict-first so it doesn't displace class rows in L1/L2.
__device__ __forceinline__ float group4(
    const float* __restrict__ emb,
    const int* __restrict__ a_idx,
    const int* __restrict__ p_idx,
    const int* __restrict__ n_idx,
    int t0, int T, int h, int s, int lane)
{
    const int tA = t0 + h;          // triplets t0, t0+1
    const int tB = t0 + 2 + h;      // triplets t0+2, t0+3
    const bool vA = (tA < T);
    const bool vB = (tB < T);
    const int cA = vA ? tA : 0;
    const int cB = vB ? tB : 0;

    const int iaA = a_idx[cA], ipA = p_idx[cA], inA = n_idx[cA];
    const int iaB = a_idx[cB], ipB = p_idx[cB], inB = n_idx[cB];

    const float4* raA = reinterpret_cast<const float4*>(emb + (size_t)iaA * 128) + s;
    const float4* rpA = reinterpret_cast<const float4*>(emb + (size_t)ipA * 128) + s;
    const float4* rnA = reinterpret_cast<const float4*>(emb + (size_t)inA * 128) + s;
    const float4* raB = reinterpret_cast<const float4*>(emb + (size_t)iaB * 128) + s;
    const float4* rpB = reinterpret_cast<const float4*>(emb + (size_t)ipB * 128) + s;
    const float4* rnB = reinterpret_cast<const float4*>(emb + (size_t)inB * 128) + s;

    const float4 aA0 = __ldg(raA),  aA1 = __ldg(raA + 16);
    const float4 pA0 = __ldg(rpA),  pA1 = __ldg(rpA + 16);
    const float4 nA0 = __ldcs(rnA), nA1 = __ldcs(rnA + 16);
    const float4 aB0 = __ldg(raB),  aB1 = __ldg(raB + 16);
    const float4 pB0 = __ldg(rpB),  pB1 = __ldg(rpB + 16);
    const float4 nB0 = __ldcs(rnB), nB1 = __ldcs(rnB + 16);

    float spA = dsq(aA0, pA0) + dsq(aA1, pA1);
    float snA = dsq(aA0, nA0) + dsq(aA1, nA1);
    float spB = dsq(aB0, pB0) + dsq(aB1, pB1);
    float snB = dsq(aB0, nB0) + dsq(aB1, nB1);

    const float rA = reduce_pair(spA, snA, lane);
    const float rB = reduce_pair(spB, snB, lane);

    float r = 0.0f;
    if ((lane & 15) == 0) {
        if (vA) r += rA;
        if (vB) r += rB;
    }
    return r;
}

// Grid-stride over 8-triplet super-groups: two straight-line group4 calls per
// trip let ptxas overlap group-B's gathers with group-A's reduction.
__global__ void __launch_bounds__(THREADS, 4) triplet_kernel(
    const float* __restrict__ emb,
    const int* __restrict__ a_idx,
    const int* __restrict__ p_idx,
    const int* __restrict__ n_idx,
    int T,
    float* __restrict__ out)
{
    const int lane = threadIdx.x & 31;
    const int h = lane >> 4;
    const int s = lane & 15;
    const int warp_in_block = threadIdx.x >> 5;

    // Virtual block id: co-resident blocks (bid % 148 equal) get consecutive vb.
    const int vb = (blockIdx.x % NSM) * BLOCKS_PER_SM + (blockIdx.x / NSM);
    const int gwarp = vb * WARPS_PER_BLOCK + warp_in_block;
    const int nwarps = gridDim.x * WARPS_PER_BLOCK;

    float acc = 0.0f;

    for (int base = gwarp * 8; base < T; base += nwarps * 8) {
        acc += group4(emb, a_idx, p_idx, n_idx, base,     T, h, s, lane);
        if (base + 4 < T)
            acc += group4(emb, a_idx, p_idx, n_idx, base + 4, T, h, s, lane);
    }

    // Full warp reduce of acc (nonzero in lanes 0 and 16).
    #pragma unroll
    for (int off = 16; off > 0; off >>= 1)
        acc += __shfl_down_sync(0xFFFFFFFFu, acc, off);

    __shared__ float warp_vals[WARPS_PER_BLOCK];
    if (lane == 0) warp_vals[warp_in_block] = acc;
    __syncthreads();

    if (warp_in_block == 0) {
        float v = (lane < WARPS_PER_BLOCK) ? warp_vals[lane] : 0.0f;
        #pragma unroll
        for (int off = 4; off > 0; off >>= 1)
            v += __shfl_down_sync(0xFFFFFFFFu, v, off);

        if (lane == 0) {
            atomicAdd(&g_sum, (double)v);
            __threadfence();
            unsigned int prev = atomicAdd(&g_count, 1u);
            if (prev == gridDim.x - 1) {
                double total = atomicAdd(&g_sum, 0.0);
                out[0] = (float)(total / (double)T);
                g_sum = 0.0;
                __threadfence();
                atomicExch(&g_count, 0u);
            }
        }
    }
}

extern "C" void kernel_launch(void* const* d_in, const int* in_sizes, int n_in,
                              void* d_out, int out_size) {
    const float* emb   = (const float*)d_in[0];
    // d_in[1] = labels (unused; mining is precomputed in the reference inputs)
    const int* a_idx   = (const int*)d_in[2];
    const int* p_idx   = (const int*)d_in[3];
    const int* n_idx   = (const int*)d_in[4];
    float* out         = (float*)d_out;

    const int T = in_sizes[2];

    // Exactly 4 resident blocks per SM on 148 SMs (the remap assumes it).
    int blocks = NSM * BLOCKS_PER_SM;
    int max_blocks = (T + WARPS_PER_BLOCK * 8 - 1) / (WARPS_PER_BLOCK * 8);
    if (blocks > max_blocks) blocks = max_blocks;
    if (blocks < 1) blocks = 1;

    triplet_kernel<<<blocks, THREADS>>>(emb, a_idx, p_idx, n_idx, T, out);
}

// round 17
// speedup vs baseline: 1.0692x; 1.0692x over previous
#include <cuda_runtime.h>
#include <cuda_bf16.h>

#define MARGIN 0.5f
#define EPS 1e-6f
#define WARPS_PER_BLOCK 8
#define THREADS (WARPS_PER_BLOCK * 32)
#define NSM 148
#define BLOCKS_PER_SM 4

// Allocation-free scratch; last finishing block resets for graph replays.
__device__ double g_sum = 0.0;
__device__ unsigned int g_count = 0u;

// Negative rows: zero L1 reuse -> don't allocate in L1 (stops them evicting
// class rows), but DEFAULT L2 policy (they are reused in L2 as other
// triplets' anchors/positives — demoting L2 was R16's mistake).
__device__ __forceinline__ float4 ldg_noL1(const float4* p)
{
    float4 v;
    asm("ld.global.nc.L1::no_allocate.v4.f32 {%0,%1,%2,%3}, [%4];"
        : "=f"(v.x), "=f"(v.y), "=f"(v.z), "=f"(v.w) : "l"(p));
    return v;
}

__device__ __forceinline__ float dsq(const float4 a, const float4 b)
{
    float d0 = a.x - b.x + EPS;
    float d1 = a.y - b.y + EPS;
    float d2 = a.z - b.z + EPS;
    float d3 = a.w - b.w + EPS;
    return fmaf(d0, d0, fmaf(d1, d1, fmaf(d2, d2, d3 * d3)));
}

// Paired reduction over a 16-lane half (5 shuffles for both sums + both sqrts).
// Returns relu(d_pos - d_neg + MARGIN) valid on lanes with (lane&15)==0.
__device__ __forceinline__ float reduce_pair(float sp, float sn, int lane)
{
    const unsigned full = 0xFFFFFFFFu;
    const bool hi = (lane & 8) != 0;
    float send = hi ? sp : sn;
    float recv = __shfl_xor_sync(full, send, 8, 16);
    float v = (hi ? sn : sp) + recv;      // lo lanes: sp pair-sum, hi lanes: sn
    v += __shfl_xor_sync(full, v, 4, 16);
    v += __shfl_xor_sync(full, v, 2, 16);
    v += __shfl_xor_sync(full, v, 1, 16);
    float d = sqrtf(v);                   // lo: d_pos, hi: d_neg
    float o = __shfl_xor_sync(full, d, 8, 16);
    return fmaxf(d - o + MARGIN, 0.0f);   // valid where !hi; read at sl==0
}

// Proven group-of-4 body (half-warp per triplet, dense 256B addressing,
// 12 gathers in flight). Anchors/positives: default __ldg. Negatives: no-L1.
__device__ __forceinline__ float group4(
    const float* __restrict__ emb,
    const int* __restrict__ a_idx,
    const int* __restrict__ p_idx,
    const int* __restrict__ n_idx,
    int t0, int T, int h, int s, int lane)
{
    const int tA = t0 + h;          // triplets t0, t0+1
    const int tB = t0 + 2 + h;      // triplets t0+2, t0+3
    const bool vA = (tA < T);
    const bool vB = (tB < T);
    const int cA = vA ? tA : 0;
    const int cB = vB ? tB : 0;

    const int iaA = a_idx[cA], ipA = p_idx[cA], inA = n_idx[cA];
    const int iaB = a_idx[cB], ipB = p_idx[cB], inB = n_idx[cB];

    const float4* raA = reinterpret_cast<const float4*>(emb + (size_t)iaA * 128) + s;
    const float4* rpA = reinterpret_cast<const float4*>(emb + (size_t)ipA * 128) + s;
    const float4* rnA = reinterpret_cast<const float4*>(emb + (size_t)inA * 128) + s;
    const float4* raB = reinterpret_cast<const float4*>(emb + (size_t)iaB * 128) + s;
    const float4* rpB = reinterpret_cast<const float4*>(emb + (size_t)ipB * 128) + s;
    const float4* rnB = reinterpret_cast<const float4*>(emb + (size_t)inB * 128) + s;

    const float4 aA0 = __ldg(raA),      aA1 = __ldg(raA + 16);
    const float4 pA0 = __ldg(rpA),      pA1 = __ldg(rpA + 16);
    const float4 nA0 = ldg_noL1(rnA),   nA1 = ldg_noL1(rnA + 16);
    const float4 aB0 = __ldg(raB),      aB1 = __ldg(raB + 16);
    const float4 pB0 = __ldg(rpB),      pB1 = __ldg(rpB + 16);
    const float4 nB0 = ldg_noL1(rnB),   nB1 = ldg_noL1(rnB + 16);

    float spA = dsq(aA0, pA0) + dsq(aA1, pA1);
    float snA = dsq(aA0, nA0) + dsq(aA1, nA1);
    float spB = dsq(aB0, pB0) + dsq(aB1, pB1);
    float snB = dsq(aB0, nB0) + dsq(aB1, nB1);

    const float rA = reduce_pair(spA, snA, lane);
    const float rB = reduce_pair(spB, snB, lane);

    float r = 0.0f;
    if ((lane & 15) == 0) {
        if (vA) r += rA;
        if (vB) r += rB;
    }
    return r;
}

// Grid-stride over 8-triplet super-groups: two straight-line group4 calls per
// trip let ptxas overlap group-B's gathers with group-A's reduction.
__global__ void __launch_bounds__(THREADS, 4) triplet_kernel(
    const float* __restrict__ emb,
    const int* __restrict__ a_idx,
    const int* __restrict__ p_idx,
    const int* __restrict__ n_idx,
    int T,
    float* __restrict__ out)
{
    const int lane = threadIdx.x & 31;
    const int h = lane >> 4;
    const int s = lane & 15;
    const int warp_in_block = threadIdx.x >> 5;

    // Virtual block id: co-resident blocks (bid % 148 equal) get consecutive vb.
    const int vb = (blockIdx.x % NSM) * BLOCKS_PER_SM + (blockIdx.x / NSM);
    const int gwarp = vb * WARPS_PER_BLOCK + warp_in_block;
    const int nwarps = gridDim.x * WARPS_PER_BLOCK;

    float acc = 0.0f;

    for (int base = gwarp * 8; base < T; base += nwarps * 8) {
        acc += group4(emb, a_idx, p_idx, n_idx, base,     T, h, s, lane);
        if (base + 4 < T)
            acc += group4(emb, a_idx, p_idx, n_idx, base + 4, T, h, s, lane);
    }

    // Full warp reduce of acc (nonzero in lanes 0 and 16).
    #pragma unroll
    for (int off = 16; off > 0; off >>= 1)
        acc += __shfl_down_sync(0xFFFFFFFFu, acc, off);

    __shared__ float warp_vals[WARPS_PER_BLOCK];
    if (lane == 0) warp_vals[warp_in_block] = acc;
    __syncthreads();

    if (warp_in_block == 0) {
        float v = (lane < WARPS_PER_BLOCK) ? warp_vals[lane] : 0.0f;
        #pragma unroll
        for (int off = 4; off > 0; off >>= 1)
            v += __shfl_down_sync(0xFFFFFFFFu, v, off);

        if (lane == 0) {
            atomicAdd(&g_sum, (double)v);
            __threadfence();
            unsigned int prev = atomicAdd(&g_count, 1u);
            if (prev == gridDim.x - 1) {
                double total = atomicAdd(&g_sum, 0.0);
                out[0] = (float)(total / (double)T);
                g_sum = 0.0;
                __threadfence();
                atomicExch(&g_count, 0u);
            }
        }
    }
}

extern "C" void kernel_launch(void* const* d_in, const int* in_sizes, int n_in,
                              void* d_out, int out_size) {
    const float* emb   = (const float*)d_in[0];
    // d_in[1] = labels (unused; mining is precomputed in the reference inputs)
    const int* a_idx   = (const int*)d_in[2];
    const int* p_idx   = (const int*)d_in[3];
    const int* n_idx   = (const int*)d_in[4];
    float* out         = (float*)d_out;

    const int T = in_sizes[2];

    // Exactly 4 resident blocks per SM on 148 SMs (the remap assumes it).
    int blocks = NSM * BLOCKS_PER_SM;
    int max_blocks = (T + WARPS_PER_BLOCK * 8 - 1) / (WARPS_PER_BLOCK * 8);
    if (blocks > max_blocks) blocks = max_blocks;
    if (blocks < 1) blocks = 1;

    triplet_kernel<<<blocks, THREADS>>>(emb, a_idx, p_idx, n_idx, T, out);
}